// round 1
// baseline (speedup 1.0000x reference)
#include <cuda_runtime.h>
#include <math.h>

// Problem constants (fixed shapes from the reference)
#define Bdim 4
#define Hdim 8
#define Tdim 512
#define Ddim 512
#define DhD  64
#define NL   64     // number of lag candidates
#define KTOP 18     // top-k lags = 2*ceil(log2(512)) = 18
#define NSLOT 19    // 1 (lag 0 / instantaneous) + KTOP
#define BH   (Bdim*Hdim)

// lags for T=512, LMAX=64: step=7 -> 1,8,...,442 then last forced to 511
__device__ __forceinline__ int lag_of(int l) { return (l == NL-1) ? (Tdim-1) : (1 + 7*l); }

// ---------------- scratch (static device memory; no runtime allocation) ----
__device__ float g_Q[BH*Tdim*DhD];                 // 4 MB, normalized in place
__device__ float g_K[BH*Tdim*DhD];                 // 4 MB, normalized in place
__device__ float g_V[BH*Tdim*DhD];                 // 4 MB
__device__ float g_cov[(size_t)BH*(NL+1)*DhD*DhD]; // 34 MB (slot NL = lag 0)
__device__ float g_score[BH*NL];
__device__ int   g_shift[BH*NSLOT];
__device__ float g_wslot[BH*NSLOT];
__device__ int   g_covsel[BH*NSLOT];
__device__ float g_attw[(size_t)BH*NSLOT*DhD*DhD]; // 10 MB
__device__ float g_outh[Bdim*Tdim*Ddim];           // 4 MB, [B,T,D] layout

// ---------------- GEMM: C[M=2048, N=512] = A[2048,512] @ W[512,512] + bias --
// 64x64 block tile, BK=16, 256 threads, 4x4 per-thread micro-tile with
// n = tx + 16*j / m = ty + 16*i mapping (conflict-free smem reads).
// a_sel: 0 -> A_ext, 1 -> g_outh.  c_sel: 0 -> C_ext (plain), 1/2/3 -> g_Q/K/V head-major.
__global__ void gemm64(const float* __restrict__ A_ext, int a_sel,
                       const float* __restrict__ W, const float* __restrict__ bias,
                       float* __restrict__ C_ext, int c_sel)
{
    __shared__ float As[16][68];  // As[k][m]
    __shared__ float Bs[16][68];  // Bs[k][n]
    const float* A = (a_sel == 0) ? A_ext : g_outh;
    const int tid = threadIdx.x;
    const int tx = tid & 15, ty = tid >> 4;
    const int m0 = blockIdx.x * 64, n0 = blockIdx.y * 64;
    float acc[4][4] = {};
    for (int k0 = 0; k0 < Ddim; k0 += 16) {
        {   // A tile: 64 rows x 16 k
            int arow = tid >> 2, ak = (tid & 3) << 2;
            float4 v = *(const float4*)(A + (size_t)(m0 + arow)*Ddim + k0 + ak);
            As[ak+0][arow] = v.x; As[ak+1][arow] = v.y;
            As[ak+2][arow] = v.z; As[ak+3][arow] = v.w;
        }
        {   // B tile: 16 rows k x 64 n
            int brow = tid >> 4, bn = (tid & 15) << 2;
            float4 v = *(const float4*)(W + (size_t)(k0 + brow)*Ddim + n0 + bn);
            *(float4*)&Bs[brow][bn] = v;
        }
        __syncthreads();
        #pragma unroll
        for (int kk = 0; kk < 16; kk++) {
            float a[4], b[4];
            #pragma unroll
            for (int i = 0; i < 4; i++) a[i] = As[kk][ty + 16*i];
            #pragma unroll
            for (int j = 0; j < 4; j++) b[j] = Bs[kk][tx + 16*j];
            #pragma unroll
            for (int i = 0; i < 4; i++)
                #pragma unroll
                for (int j = 0; j < 4; j++)
                    acc[i][j] = fmaf(a[i], b[j], acc[i][j]);
        }
        __syncthreads();
    }
    #pragma unroll
    for (int i = 0; i < 4; i++) {
        int m = m0 + ty + 16*i;
        #pragma unroll
        for (int j = 0; j < 4; j++) {
            int n = n0 + tx + 16*j;
            float v = acc[i][j] + bias[n];
            if (c_sel == 0) {
                C_ext[(size_t)m*Ddim + n] = v;
            } else {
                float* C = (c_sel == 1) ? g_Q : (c_sel == 2) ? g_K : g_V;
                int b = m >> 9, t = m & (Tdim-1), h = n >> 6, c = n & (DhD-1);
                C[(((size_t)(b*Hdim + h))*Tdim + t)*DhD + c] = v;
            }
        }
    }
}

// ---------------- L2-normalize Q and K over the time axis --------------------
__global__ void normalize_kernel()
{
    int bh = blockIdx.x;
    float* base = (blockIdx.y ? g_K : g_Q) + (size_t)bh*Tdim*DhD;
    int d = threadIdx.x; // 64
    float s = 0.f;
    for (int t = 0; t < Tdim; t++) { float v = base[t*DhD + d]; s = fmaf(v, v, s); }
    float inv = 1.0f / sqrtf(fmaxf(s, 1e-8f));
    for (int t = 0; t < Tdim; t++) base[t*DhD + d] *= inv;
}

// ---------------- cov[bh][l][d][c] = sum_t Khat[(t-lag)%T][d] * Qhat[t][c] ---
// l in [0,64]; l==64 is lag 0 (the instantaneous cov0). Fuses the lag score.
__global__ void cov_kernel(const float* __restrict__ lam_ptr)
{
    __shared__ float Ks[32][68];
    __shared__ float Qs[32][68];
    __shared__ float red1[256];
    __shared__ float red2[256];
    const int l = blockIdx.x, bh = blockIdx.y;
    const int lag = (l == NL) ? 0 : lag_of(l);
    const float* Kb = g_K + (size_t)bh*Tdim*DhD;
    const float* Qb = g_Q + (size_t)bh*Tdim*DhD;
    const int tid = threadIdx.x, tx = tid & 15, ty = tid >> 4;
    float acc[4][4] = {};
    for (int t0 = 0; t0 < Tdim; t0 += 32) {
        #pragma unroll
        for (int p = 0; p < 2; p++) {
            int fi = tid + p*256;
            int row = fi >> 4, c4 = (fi & 15) << 2;
            *(float4*)&Qs[row][c4] = *(const float4*)(Qb + (t0 + row)*DhD + c4);
            int src = (t0 + row - lag + Tdim) & (Tdim - 1);
            *(float4*)&Ks[row][c4] = *(const float4*)(Kb + src*DhD + c4);
        }
        __syncthreads();
        #pragma unroll
        for (int tt = 0; tt < 32; tt++) {
            float a[4], b[4];
            #pragma unroll
            for (int i = 0; i < 4; i++) a[i] = Ks[tt][ty + 16*i];
            #pragma unroll
            for (int j = 0; j < 4; j++) b[j] = Qs[tt][tx + 16*j];
            #pragma unroll
            for (int i = 0; i < 4; i++)
                #pragma unroll
                for (int j = 0; j < 4; j++)
                    acc[i][j] = fmaf(a[i], b[j], acc[i][j]);
        }
        __syncthreads();
    }
    float* covp = g_cov + ((size_t)bh*(NL+1) + l) * (DhD*DhD);
    float tot = 0.f, dia = 0.f;
    #pragma unroll
    for (int i = 0; i < 4; i++)
        #pragma unroll
        for (int j = 0; j < 4; j++) {
            int d = ty + 16*i, c = tx + 16*j;
            covp[d*DhD + c] = acc[i][j];
            float av = fabsf(acc[i][j]);
            tot += av;
            if (d == c) dia += av;
        }
    if (l < NL) {
        red1[tid] = tot; red2[tid] = dia;
        __syncthreads();
        for (int s = 128; s > 0; s >>= 1) {
            if (tid < s) { red1[tid] += red1[tid+s]; red2[tid] += red2[tid+s]; }
            __syncthreads();
        }
        if (tid == 0) {
            float lam = fminf(fmaxf(*lam_ptr, 0.f), 1.f);
            g_score[bh*NL + l] = lam*red2[0] + (1.f - lam)*(red1[0] - red2[0]);
        }
    }
}

// ---------------- top-18 lag selection + slot weights ------------------------
__global__ void topk_kernel(const float* __restrict__ lt_lag,
                            const float* __restrict__ beta_ptr)
{
    int bh = threadIdx.x;
    if (bh >= BH) return;
    float sc[NL];
    for (int l = 0; l < NL; l++) sc[l] = g_score[bh*NL + l];
    float selVal[KTOP]; int selIdx[KTOP];
    for (int k = 0; k < KTOP; k++) {
        float best = -3.4e38f; int bi = 0;
        for (int l = 0; l < NL; l++) if (sc[l] > best) { best = sc[l]; bi = l; }
        selVal[k] = best; selIdx[k] = bi; sc[bi] = -3.4e38f;
    }
    float tl = fmaxf(expf(*lt_lag), 1e-4f);
    float mx = selVal[0];
    float e[KTOP], esum = 0.f;
    for (int k = 0; k < KTOP; k++) { e[k] = expf((selVal[k] - mx)/tl); esum += e[k]; }
    float beta = fminf(fmaxf(*beta_ptr, 0.f), 1.f);
    g_shift[bh*NSLOT]  = 0;
    g_wslot[bh*NSLOT]  = 1.f - beta;
    g_covsel[bh*NSLOT] = NL;
    for (int k = 0; k < KTOP; k++) {
        g_shift[bh*NSLOT + 1 + k]  = lag_of(selIdx[k]);
        g_wslot[bh*NSLOT + 1 + k]  = beta * e[k] / esum;
        g_covsel[bh*NSLOT + 1 + k] = selIdx[k];
    }
}

// ---------------- attw[s] = weight_s * softmax_c(cov_sel / tau) --------------
__global__ void att_kernel(const float* __restrict__ log_tau_ptr)
{
    const int s = blockIdx.x, bh = blockIdx.y;
    const int l = g_covsel[bh*NSLOT + s];
    const float w = g_wslot[bh*NSLOT + s];
    const float invtau = 1.0f / fmaxf(expf(*log_tau_ptr), 1e-4f);
    const float* covp = g_cov + ((size_t)bh*(NL+1) + l)*(DhD*DhD);
    float* outp = g_attw + ((size_t)bh*NSLOT + s)*(DhD*DhD);
    int warp = threadIdx.x >> 5, lane = threadIdx.x & 31;
    for (int d = warp; d < DhD; d += 8) {
        float v0 = covp[d*DhD + lane]      * invtau;
        float v1 = covp[d*DhD + lane + 32] * invtau;
        float m = fmaxf(v0, v1);
        #pragma unroll
        for (int o = 16; o > 0; o >>= 1) m = fmaxf(m, __shfl_xor_sync(0xffffffffu, m, o));
        float e0 = expf(v0 - m), e1 = expf(v1 - m);
        float ss = e0 + e1;
        #pragma unroll
        for (int o = 16; o > 0; o >>= 1) ss += __shfl_xor_sync(0xffffffffu, ss, o);
        float f = w / ss;
        outp[d*DhD + lane]      = e0 * f;
        outp[d*DhD + lane + 32] = e1 * f;
    }
}

// ---------------- out_h[t,c] = sum_s sum_d V[(t-shift_s)%T, d] * attw_s[d,c] --
__global__ void contrib_kernel()
{
    __shared__ float Att[64][68];
    __shared__ float Vs[64][68];
    const int bh = blockIdx.y, t0 = blockIdx.x * 64;
    const int bb = bh >> 3, hh = bh & 7;
    const float* Vb = g_V + (size_t)bh*Tdim*DhD;
    const int tid = threadIdx.x, tx = tid & 15, ty = tid >> 4;
    float acc[4][4] = {};
    for (int s = 0; s < NSLOT; s++) {
        const int shift = g_shift[bh*NSLOT + s];
        const float* ap = g_attw + ((size_t)bh*NSLOT + s)*(DhD*DhD);
        #pragma unroll
        for (int p = 0; p < 4; p++) {
            int fi = tid + p*256;
            int row = fi >> 4, c4 = (fi & 15) << 2;
            *(float4*)&Att[row][c4] = *(const float4*)(ap + row*DhD + c4);
            int src = (t0 + row - shift + Tdim) & (Tdim - 1);
            *(float4*)&Vs[row][c4] = *(const float4*)(Vb + src*DhD + c4);
        }
        __syncthreads();
        #pragma unroll 8
        for (int dd = 0; dd < 64; dd++) {
            float a[4], b[4];
            #pragma unroll
            for (int i = 0; i < 4; i++) a[i] = Vs[ty + 16*i][dd];
            #pragma unroll
            for (int j = 0; j < 4; j++) b[j] = Att[dd][tx + 16*j];
            #pragma unroll
            for (int i = 0; i < 4; i++)
                #pragma unroll
                for (int j = 0; j < 4; j++)
                    acc[i][j] = fmaf(a[i], b[j], acc[i][j]);
        }
        __syncthreads();
    }
    #pragma unroll
    for (int i = 0; i < 4; i++) {
        int t = t0 + ty + 16*i;
        #pragma unroll
        for (int j = 0; j < 4; j++) {
            int c = tx + 16*j;
            g_outh[((size_t)(bb*Tdim + t))*Ddim + hh*DhD + c] = acc[i][j];
        }
    }
}

// ---------------- launch ------------------------------------------------------
extern "C" void kernel_launch(void* const* d_in, const int* in_sizes, int n_in,
                              void* d_out, int out_size)
{
    const float* x           = (const float*)d_in[0];
    const float* Wq          = (const float*)d_in[1];
    const float* bq          = (const float*)d_in[2];
    const float* Wk          = (const float*)d_in[3];
    const float* bk          = (const float*)d_in[4];
    const float* Wv          = (const float*)d_in[5];
    const float* bv          = (const float*)d_in[6];
    const float* Wo          = (const float*)d_in[7];
    const float* bo          = (const float*)d_in[8];
    const float* log_tau     = (const float*)d_in[9];
    const float* lambda_auto = (const float*)d_in[10];
    const float* beta_lag    = (const float*)d_in[11];
    const float* log_tau_lag = (const float*)d_in[12];
    float* out = (float*)d_out;

    dim3 ggrid(Bdim*Tdim/64, Ddim/64);   // 32 x 8

    gemm64<<<ggrid, 256>>>(x, 0, Wq, bq, nullptr, 1);
    gemm64<<<ggrid, 256>>>(x, 0, Wk, bk, nullptr, 2);
    gemm64<<<ggrid, 256>>>(x, 0, Wv, bv, nullptr, 3);
    normalize_kernel<<<dim3(BH, 2), DhD>>>();
    cov_kernel<<<dim3(NL+1, BH), 256>>>(lambda_auto);
    topk_kernel<<<1, 32>>>(log_tau_lag, beta_lag);
    att_kernel<<<dim3(NSLOT, BH), 256>>>(log_tau);
    contrib_kernel<<<dim3(Tdim/64, BH), 256>>>();
    gemm64<<<ggrid, 256>>>(nullptr, 1, Wo, bo, out, 0);
}